// round 3
// baseline (speedup 1.0000x reference)
#include <cuda_runtime.h>
#include <cuda_bf16.h>
#include <math.h>
#include <math_constants.h>

// Problem constants
#define BQ  8
#define HQ  8
#define BH  64          // B*H
#define LQ  2048
#define DQ  64
#define NSEL 40         // num selected queries == num sampled keys
#define SCALE 0.125f    // 64^-0.5
#define NEG_INF (-CUDART_INF_F)

// ---------------- scratch (device globals; no allocation allowed) ----------
__device__ float g_measure[BH * LQ];
__device__ int   g_topidx[BH * NSEL];
__device__ float g_rowMaxPart[BH * 8 * NSEL];
__device__ float g_rowSumPart[BH * 8 * NSEL];
__device__ float g_rowMax[BH * NSEL];
__device__ float g_rowInv[BH * NSEL];
__device__ float g_outSel[BH * NSEL * DQ];
__device__ float g_chunkSum[BH * 16 * DQ];

// ============================================================================
// K1: measure[bh][i] = max_j (q_i . k_{ridx[i,j]}) - (sum_j ...) / L
// Lane-per-key: warp = 1 query. Lane l computes the FULL 64-dim dot for key l
// (lanes 0..7 also handle key 32+l). K row read as 16 independent LDG.128
// (high MLP), Q broadcast from smem. Single 5-step butterfly at the end.
// ============================================================================
__global__ __launch_bounds__(256) void k_measure(const float* __restrict__ q,
                                                 const float* __restrict__ k,
                                                 const int* __restrict__ ridx) {
    __shared__ float qsh[8][DQ];
    const unsigned F = 0xffffffffu;
    int wib = threadIdx.x >> 5, lane = threadIdx.x & 31;
    int wg = blockIdx.x * 8 + wib;
    int bh = wg >> 11, i = wg & 2047;

    // stage this warp's q row into smem (2 floats per lane)
    {
        const float2* qrow = reinterpret_cast<const float2*>(q + ((size_t)bh * LQ + i) * DQ);
        reinterpret_cast<float2*>(qsh[wib])[lane] = qrow[lane];
    }
    __syncwarp();

    int r0 = ridx[i * NSEL + lane];
    int r1 = (lane < NSEL - 32) ? ridx[i * NSEL + 32 + lane] : r0;

    const float4* kb4 = reinterpret_cast<const float4*>(k + (size_t)bh * LQ * DQ);
    const float4* qs4 = reinterpret_cast<const float4*>(qsh[wib]);
    const float4* ka = kb4 + (size_t)r0 * (DQ / 4);
    const float4* kc = kb4 + (size_t)r1 * (DQ / 4);

    float acc0 = 0.0f, acc1 = 0.0f;
#pragma unroll
    for (int d4 = 0; d4 < DQ / 4; d4++) {
        float4 qv = qs4[d4];      // broadcast LDS
        float4 a = ka[d4];
        float4 c = kc[d4];
        acc0 = fmaf(qv.x, a.x, acc0); acc0 = fmaf(qv.y, a.y, acc0);
        acc0 = fmaf(qv.z, a.z, acc0); acc0 = fmaf(qv.w, a.w, acc0);
        acc1 = fmaf(qv.x, c.x, acc1); acc1 = fmaf(qv.y, c.y, acc1);
        acc1 = fmaf(qv.z, c.z, acc1); acc1 = fmaf(qv.w, c.w, acc1);
    }

    bool has2 = (lane < NSEL - 32);
    float lm = has2 ? fmaxf(acc0, acc1) : acc0;
    float ls = has2 ? (acc0 + acc1) : acc0;
#pragma unroll
    for (int st = 16; st >= 1; st >>= 1) {
        lm = fmaxf(lm, __shfl_xor_sync(F, lm, st));
        ls += __shfl_xor_sync(F, ls, st);
    }
    if (lane == 0) g_measure[bh * LQ + i] = lm - ls * (1.0f / (float)LQ);
}

// ============================================================================
// K2: per (b,h) top-40 of 2048 via 4-pass byte radix select + rank sort.
// Matches jax.lax.top_k: descending value, ties -> lower index first.
// One block (256 thr) per bh.
// ============================================================================
__global__ void k_topk() {
    __shared__ unsigned ukey[LQ];
    __shared__ int hist[256];
    __shared__ int ssum[256];
    __shared__ int wsum[8];
    __shared__ int s_chosen;
    __shared__ int s_target;
    __shared__ int cnt_gt;
    __shared__ unsigned selKey[64];
    __shared__ int selIdx[64];
    __shared__ int tcnt[256];

    int bh = blockIdx.x, t = threadIdx.x, lane = t & 31, w = t >> 5;

    for (int e = t; e < LQ; e += 256) {
        unsigned b = __float_as_uint(g_measure[bh * LQ + e]);
        ukey[e] = (b & 0x80000000u) ? ~b : (b | 0x80000000u);
    }
    if (t == 0) { s_target = NSEL; cnt_gt = 0; }
    __syncthreads();

    unsigned prefix = 0;
    for (int pass = 3; pass >= 0; pass--) {
        int shift = pass * 8;
        hist[t] = 0;
        __syncthreads();
        unsigned himask = (pass == 3) ? 0u : (0xFFFFFFFFu << (shift + 8));
        for (int e = t; e < LQ; e += 256) {
            unsigned u = ukey[e];
            if ((u & himask) == (prefix & himask))
                atomicAdd(&hist[(u >> shift) & 255], 1);
        }
        __syncthreads();
        // suffix sums S[b] = count of candidate keys with byte >= b
        int r = 255 - t;
        int x = hist[r];
#pragma unroll
        for (int o = 1; o < 32; o <<= 1) {
            int y = __shfl_up_sync(0xffffffffu, x, o);
            if (lane >= o) x += y;
        }
        if (lane == 31) wsum[w] = x;
        __syncthreads();
        if (w == 0 && lane < 8) {
            int y = wsum[lane];
#pragma unroll
            for (int o = 1; o < 8; o <<= 1) {
                int z = __shfl_up_sync(0xffu, y, o);
                if (lane >= o) y += z;
            }
            wsum[lane] = y;
        }
        __syncthreads();
        int S = x + (w > 0 ? wsum[w - 1] : 0);
        ssum[r] = S;
        __syncthreads();
        int target = s_target;
        int Sb = ssum[t];
        int Sb1 = (t == 255) ? 0 : ssum[t + 1];
        if (Sb >= target && Sb1 < target) s_chosen = t;
        __syncthreads();
        int chosen = s_chosen;
        prefix |= ((unsigned)chosen) << shift;
        if (t == 0) s_target = target - ((chosen == 255) ? 0 : ssum[chosen + 1]);
        __syncthreads();
    }
    unsigned T = prefix;
    int need_eq = s_target;
    int count_gt = NSEL - need_eq;

    // collect strictly-greater + count ties per thread (blocked distribution)
    int mytie = 0;
#pragma unroll
    for (int e2 = 0; e2 < 8; e2++) {
        int e = t * 8 + e2;
        unsigned u = ukey[e];
        if (u > T) {
            int p = atomicAdd(&cnt_gt, 1);
            selKey[p] = u; selIdx[p] = e;
        } else if (u == T) mytie++;
    }
    tcnt[t] = mytie;
    __syncthreads();
    // exclusive scan tie counts -> emit lowest-index ties
    {
        int x = tcnt[t];
#pragma unroll
        for (int o = 1; o < 32; o <<= 1) {
            int y = __shfl_up_sync(0xffffffffu, x, o);
            if (lane >= o) x += y;
        }
        if (lane == 31) wsum[w] = x;
        __syncthreads();
        if (w == 0 && lane < 8) {
            int y = wsum[lane];
#pragma unroll
            for (int o = 1; o < 8; o <<= 1) {
                int z = __shfl_up_sync(0xffu, y, o);
                if (lane >= o) y += z;
            }
            wsum[lane] = y;
        }
        __syncthreads();
        int run = x - tcnt[t] + (w > 0 ? wsum[w - 1] : 0);
#pragma unroll
        for (int e2 = 0; e2 < 8; e2++) {
            int e = t * 8 + e2;
            if (ukey[e] == T) {
                if (run < need_eq) { selKey[count_gt + run] = T; selIdx[count_gt + run] = e; }
                run++;
            }
        }
    }
    __syncthreads();
    // rank sort 40: (key desc, idx asc)
    if (t < NSEL) {
        unsigned mk = selKey[t]; int mi = selIdx[t];
        int rank = 0;
        for (int f = 0; f < NSEL; f++) {
            unsigned fk = selKey[f]; int fi = selIdx[f];
            if (fk > mk || (fk == mk && fi < mi)) rank++;
        }
        g_topidx[bh * NSEL + rank] = mi;
    }
}

// ============================================================================
// K3: logits = (q_sel @ k^T)*SCALE with causal mask (j > idx -> -inf),
// written to attn buffer; also per-row partial max / sumexp per 256-key split.
// grid (BH, 8), block 256. Register-tiled 40x128 per subtile.
// ============================================================================
__global__ void k_logits(const float* __restrict__ q,
                         const float* __restrict__ k,
                         float* __restrict__ attn) {
    __shared__ float qs[NSEL * DQ];        // 40x64
    __shared__ float ks[128 * 65];         // padded
    __shared__ int   sidx[NSEL];

    int bh = blockIdx.x, js = blockIdx.y, t = threadIdx.x;
    if (t < NSEL) sidx[t] = g_topidx[bh * NSEL + t];
    __syncthreads();

    for (int e = t; e < NSEL * DQ; e += 256) {
        int s = e >> 6, d = e & 63;
        qs[e] = q[((size_t)bh * LQ + sidx[s]) * DQ + d];
    }

    float* attnBH = attn + (size_t)bh * NSEL * LQ;
    int tx = t & 63, ty = t >> 6;   // tx: key col base, ty: 0..3 row group

    for (int sub = 0; sub < 2; sub++) {
        int j0 = js * 256 + sub * 128;
        __syncthreads();
        for (int e = t; e < 128 * DQ; e += 256) {
            int r = e >> 6, d = e & 63;
            ks[r * 65 + d] = k[((size_t)bh * LQ + j0 + r) * DQ + d];
        }
        __syncthreads();

        float acc[10][2];
#pragma unroll
        for (int r = 0; r < 10; r++) { acc[r][0] = 0.0f; acc[r][1] = 0.0f; }

#pragma unroll 4
        for (int d = 0; d < DQ; d++) {
            float k0 = ks[tx * 65 + d];
            float k1 = ks[(tx + 64) * 65 + d];
#pragma unroll
            for (int r = 0; r < 10; r++) {
                float qv = qs[(ty + 4 * r) * DQ + d];
                acc[r][0] = fmaf(qv, k0, acc[r][0]);
                acc[r][1] = fmaf(qv, k1, acc[r][1]);
            }
        }
#pragma unroll
        for (int r = 0; r < 10; r++) {
            int s = ty + 4 * r;
            int lim = sidx[s];
            int jg0 = j0 + tx;
            int jg1 = j0 + tx + 64;
            attnBH[(size_t)s * LQ + jg0] = (jg0 > lim) ? NEG_INF : acc[r][0] * SCALE;
            attnBH[(size_t)s * LQ + jg1] = (jg1 > lim) ? NEG_INF : acc[r][1] * SCALE;
        }
    }
    __syncthreads();   // make our global logit writes visible block-wide

    // partial softmax stats over this block's 256-key span
    int w = t >> 5, lane = t & 31;
    for (int rr = 0; rr < 5; rr++) {
        int s = w + 8 * rr;
        size_t base = (size_t)s * LQ + js * 256;
        float m = NEG_INF;
#pragma unroll
        for (int u = 0; u < 8; u++) m = fmaxf(m, attnBH[base + lane + 32 * u]);
        m = fmaxf(m, __shfl_xor_sync(0xffffffffu, m, 16));
        m = fmaxf(m, __shfl_xor_sync(0xffffffffu, m, 8));
        m = fmaxf(m, __shfl_xor_sync(0xffffffffu, m, 4));
        m = fmaxf(m, __shfl_xor_sync(0xffffffffu, m, 2));
        m = fmaxf(m, __shfl_xor_sync(0xffffffffu, m, 1));
        float ssum = 0.0f;
        if (m > NEG_INF) {
#pragma unroll
            for (int u = 0; u < 8; u++) ssum += expf(attnBH[base + lane + 32 * u] - m);
        }
        ssum += __shfl_xor_sync(0xffffffffu, ssum, 16);
        ssum += __shfl_xor_sync(0xffffffffu, ssum, 8);
        ssum += __shfl_xor_sync(0xffffffffu, ssum, 4);
        ssum += __shfl_xor_sync(0xffffffffu, ssum, 2);
        ssum += __shfl_xor_sync(0xffffffffu, ssum, 1);
        if (lane == 0) {
            g_rowMaxPart[(bh * 8 + js) * NSEL + s] = m;
            g_rowSumPart[(bh * 8 + js) * NSEL + s] = ssum;
        }
    }
}

// ============================================================================
// K3b: combine partial stats -> final rowMax / 1/rowSum; zero outSel scratch
// ============================================================================
__global__ void k_combine() {
    int bh = blockIdx.x, t = threadIdx.x;
    if (t < NSEL) {
        float fm = NEG_INF;
#pragma unroll
        for (int p = 0; p < 8; p++)
            fm = fmaxf(fm, g_rowMaxPart[(bh * 8 + p) * NSEL + t]);
        float fs = 0.0f;
#pragma unroll
        for (int p = 0; p < 8; p++) {
            float pm = g_rowMaxPart[(bh * 8 + p) * NSEL + t];
            float ps = g_rowSumPart[(bh * 8 + p) * NSEL + t];
            fs += ps * expf(pm - fm);
        }
        g_rowMax[bh * NSEL + t] = fm;
        g_rowInv[bh * NSEL + t] = 1.0f / fs;
    }
    for (int e = t; e < NSEL * DQ; e += 64) g_outSel[bh * NSEL * DQ + e] = 0.0f;
}

// ============================================================================
// cumsum(v, axis=L): 3-pass chunk scan (chunk = 128 rows, 16 chunks)
// ============================================================================
__global__ void k_csumA(const float* __restrict__ v) {       // grid (BH,16), 256 thr
    int bh = blockIdx.x, c = blockIdx.y, t = threadIdx.x;
    int d = t & 63, g = t >> 6;
    const float* base = v + ((size_t)bh * LQ + c * 128) * DQ;
    float s = 0.0f;
#pragma unroll 8
    for (int r = g * 32; r < g * 32 + 32; r++) s += base[(size_t)r * DQ + d];
    __shared__ float red[256];
    red[t] = s;
    __syncthreads();
    if (g == 0)
        g_chunkSum[(bh * 16 + c) * DQ + d] = red[d] + red[64 + d] + red[128 + d] + red[192 + d];
}

__global__ void k_csumB() {                                  // grid BH, 64 thr
    int bh = blockIdx.x, d = threadIdx.x;
    float run = 0.0f;
#pragma unroll
    for (int c = 0; c < 16; c++) {
        float x = g_chunkSum[(bh * 16 + c) * DQ + d];
        g_chunkSum[(bh * 16 + c) * DQ + d] = run;   // exclusive
        run += x;
    }
}

__global__ void k_csumC(const float* __restrict__ v, float* __restrict__ out) { // grid (BH,16), 64 thr
    int bh = blockIdx.x, c = blockIdx.y, d = threadIdx.x;
    const float* base = v + ((size_t)bh * LQ + c * 128) * DQ;
    float* obase = out + ((size_t)bh * LQ + c * 128) * DQ;
    float run = g_chunkSum[(bh * 16 + c) * DQ + d];
#pragma unroll 8
    for (int r = 0; r < 128; r++) {
        run += base[(size_t)r * DQ + d];
        obase[(size_t)r * DQ + d] = run;
    }
}

// ============================================================================
// K4: probs = softmax(logits) written in place to attn; out_sel += P @ V
// grid (BH, 4 jsplits of 512 keys), block 256. 8 inner tiles of 64 keys.
// ============================================================================
__global__ void k_pv(const float* __restrict__ v, float* __restrict__ attn) {
    __shared__ float vs[64 * DQ];     // 16 KB
    __shared__ float ps[NSEL * 64];   // 10 KB
    __shared__ float sMax[NSEL], sInv[NSEL];

    int bh = blockIdx.x, js = blockIdx.y, t = threadIdx.x;
    if (t < NSEL) { sMax[t] = g_rowMax[bh * NSEL + t]; sInv[t] = g_rowInv[bh * NSEL + t]; }

    float* attnBH = attn + (size_t)bh * NSEL * LQ;
    const float* vBH = v + (size_t)bh * LQ * DQ;

    int tx = t & 31, ty = t >> 5;
    int g = ty >> 2;       // jj half
    int sy = ty & 3;       // row group

    float acc[10][2];
#pragma unroll
    for (int r = 0; r < 10; r++) { acc[r][0] = 0.0f; acc[r][1] = 0.0f; }
    __syncthreads();

    for (int tile = 0; tile < 8; tile++) {
        int j0 = js * 512 + tile * 64;
        __syncthreads();
        const float4* vsrc = reinterpret_cast<const float4*>(vBH + (size_t)j0 * DQ);
        float4* vdst = reinterpret_cast<float4*>(vs);
        for (int e = t; e < 64 * DQ / 4; e += 256) vdst[e] = vsrc[e];
        for (int e = t; e < NSEL * 64; e += 256) {
            int s = e >> 6, jj = e & 63;
            size_t a = (size_t)s * LQ + j0 + jj;
            float l = attnBH[a];
            float p = expf(l - sMax[s]) * sInv[s];
            attnBH[a] = p;
            ps[e] = p;
        }
        __syncthreads();
#pragma unroll 4
        for (int jl = g * 32; jl < g * 32 + 32; jl++) {
            float2 vv = *reinterpret_cast<const float2*>(&vs[jl * DQ + 2 * tx]);
#pragma unroll
            for (int r = 0; r < 10; r++) {
                float p = ps[(sy + 4 * r) * 64 + jl];
                acc[r][0] = fmaf(p, vv.x, acc[r][0]);
                acc[r][1] = fmaf(p, vv.y, acc[r][1]);
            }
        }
    }
#pragma unroll
    for (int r = 0; r < 10; r++) {
        int s = sy + 4 * r;
        atomicAdd(&g_outSel[(bh * NSEL + s) * DQ + 2 * tx], acc[r][0]);
        atomicAdd(&g_outSel[(bh * NSEL + s) * DQ + 2 * tx + 1], acc[r][1]);
    }
}

// ============================================================================
// K6: scatter out_sel rows into out at the selected positions
// ============================================================================
__global__ void k_scatter(float* __restrict__ out) {   // grid BH, 256 thr
    int bh = blockIdx.x, t = threadIdx.x;
    for (int e = t; e < NSEL * DQ; e += 256) {
        int s = e >> 6, d = e & 63;
        out[((size_t)bh * LQ + g_topidx[bh * NSEL + s]) * DQ + d] =
            g_outSel[bh * NSEL * DQ + e];
    }
}

// ============================================================================
extern "C" void kernel_launch(void* const* d_in, const int* in_sizes, int n_in,
                              void* d_out, int out_size) {
    const float* q = (const float*)d_in[0];
    const float* k = (const float*)d_in[1];
    const float* v = (const float*)d_in[2];
    const int* ridx = (const int*)d_in[3];

    float* out  = (float*)d_out;                        // [BH, L, D]
    float* attn = out + (size_t)BH * LQ * DQ;           // [BH, NSEL, L]

    // 1. measure (lane-per-key gather)
    k_measure<<<(BH * LQ) / 8, 256>>>(q, k, ridx);
    // 2. top-k selection (radix select)
    k_topk<<<BH, 256>>>();
    // 3. logits + partial softmax stats
    {
        dim3 grid(BH, 8);
        k_logits<<<grid, 256>>>(q, k, attn);
    }
    // 3b. combine stats, zero out_sel
    k_combine<<<BH, 64>>>();
    // 5. cumsum(v) -> out
    {
        dim3 grid(BH, 16);
        k_csumA<<<grid, 256>>>(v);
        k_csumB<<<BH, 64>>>();
        k_csumC<<<grid, 64>>>(v, out);
    }
    // 4. softmax probs (in place) + P@V partial accumulation
    {
        dim3 grid(BH, 4);
        k_pv<<<grid, 256>>>(v, attn);
    }
    // 6. scatter selected rows into out
    k_scatter<<<BH, 256>>>(out);
}

// round 4
// speedup vs baseline: 2.1005x; 2.1005x over previous
#include <cuda_runtime.h>
#include <cuda_bf16.h>
#include <math.h>
#include <math_constants.h>

// Problem constants
#define BQ  8
#define HQ  8
#define BH  64          // B*H
#define LQ  2048
#define DQ  64
#define NSEL 40         // num selected queries == num sampled keys
#define SCALE 0.125f    // 64^-0.5
#define NEG_INF (-CUDART_INF_F)

// ---------------- scratch (device globals; no allocation allowed) ----------
__device__ float g_measure[BH * LQ];
__device__ int   g_topidx[BH * NSEL];
__device__ float g_rowMaxPart[BH * 8 * NSEL];
__device__ float g_rowSumPart[BH * 8 * NSEL];
__device__ float g_rowMax[BH * NSEL];
__device__ float g_rowInv[BH * NSEL];
__device__ float g_outSel[BH * NSEL * DQ];
__device__ float g_chunkSum[BH * 16 * DQ];

// ============================================================================
// K1: measure[bh][i] = max_j (q_i . k_{ridx[i,j]}) - (sum_j ...) / L
// Warp per query (coalesced 256B row gathers, as in R1) BUT keys processed
// 4 at a time: int4 index load, 4 independent row loads, 4 interleaved
// butterfly reductions -> serial chain cut ~4x, MLP ~4x.
// ============================================================================
__global__ __launch_bounds__(256) void k_measure(const float* __restrict__ q,
                                                 const float* __restrict__ k,
                                                 const int* __restrict__ ridx) {
    const unsigned F = 0xffffffffu;
    int warp = (blockIdx.x * blockDim.x + threadIdx.x) >> 5;
    int lane = threadIdx.x & 31;
    int bh = warp >> 11;
    int i  = warp & 2047;

    const float2* q2 = reinterpret_cast<const float2*>(q) + ((size_t)(bh * LQ + i)) * 32;
    float2 qv = q2[lane];
    const float2* kb = reinterpret_cast<const float2*>(k) + (size_t)bh * LQ * 32;
    const int4* r4p = reinterpret_cast<const int4*>(ridx + i * NSEL);   // 40 ints = 10 int4

    float m = NEG_INF;
    float s = 0.0f;
#pragma unroll
    for (int h = 0; h < NSEL / 4; h++) {
        int4 r4 = r4p[h];
        float2 k0 = kb[(size_t)r4.x * 32 + lane];
        float2 k1 = kb[(size_t)r4.y * 32 + lane];
        float2 k2 = kb[(size_t)r4.z * 32 + lane];
        float2 k3 = kb[(size_t)r4.w * 32 + lane];
        float d0 = qv.x * k0.x + qv.y * k0.y;
        float d1 = qv.x * k1.x + qv.y * k1.y;
        float d2 = qv.x * k2.x + qv.y * k2.y;
        float d3 = qv.x * k3.x + qv.y * k3.y;
#pragma unroll
        for (int st = 16; st >= 1; st >>= 1) {
            d0 += __shfl_xor_sync(F, d0, st);
            d1 += __shfl_xor_sync(F, d1, st);
            d2 += __shfl_xor_sync(F, d2, st);
            d3 += __shfl_xor_sync(F, d3, st);
        }
        m = fmaxf(fmaxf(fmaxf(m, d0), fmaxf(d1, d2)), d3);
        s += (d0 + d1) + (d2 + d3);
    }
    if (lane == 0) g_measure[warp] = m - s * (1.0f / (float)LQ);
}

// ============================================================================
// K2: per (b,h) top-40 of 2048 via 4-pass byte radix select + rank sort.
// Matches jax.lax.top_k: descending value, ties -> lower index first.
// One block (256 thr) per bh.
// ============================================================================
__global__ void k_topk() {
    __shared__ unsigned ukey[LQ];
    __shared__ int hist[256];
    __shared__ int ssum[256];
    __shared__ int wsum[8];
    __shared__ int s_chosen;
    __shared__ int s_target;
    __shared__ int cnt_gt;
    __shared__ unsigned selKey[64];
    __shared__ int selIdx[64];
    __shared__ int tcnt[256];

    int bh = blockIdx.x, t = threadIdx.x, lane = t & 31, w = t >> 5;

    for (int e = t; e < LQ; e += 256) {
        unsigned b = __float_as_uint(g_measure[bh * LQ + e]);
        ukey[e] = (b & 0x80000000u) ? ~b : (b | 0x80000000u);
    }
    if (t == 0) { s_target = NSEL; cnt_gt = 0; }
    __syncthreads();

    unsigned prefix = 0;
    for (int pass = 3; pass >= 0; pass--) {
        int shift = pass * 8;
        hist[t] = 0;
        __syncthreads();
        unsigned himask = (pass == 3) ? 0u : (0xFFFFFFFFu << (shift + 8));
        for (int e = t; e < LQ; e += 256) {
            unsigned u = ukey[e];
            if ((u & himask) == (prefix & himask))
                atomicAdd(&hist[(u >> shift) & 255], 1);
        }
        __syncthreads();
        // suffix sums S[b] = count of candidate keys with byte >= b
        int r = 255 - t;
        int x = hist[r];
#pragma unroll
        for (int o = 1; o < 32; o <<= 1) {
            int y = __shfl_up_sync(0xffffffffu, x, o);
            if (lane >= o) x += y;
        }
        if (lane == 31) wsum[w] = x;
        __syncthreads();
        if (w == 0 && lane < 8) {
            int y = wsum[lane];
#pragma unroll
            for (int o = 1; o < 8; o <<= 1) {
                int z = __shfl_up_sync(0xffu, y, o);
                if (lane >= o) y += z;
            }
            wsum[lane] = y;
        }
        __syncthreads();
        int S = x + (w > 0 ? wsum[w - 1] : 0);
        ssum[r] = S;
        __syncthreads();
        int target = s_target;
        int Sb = ssum[t];
        int Sb1 = (t == 255) ? 0 : ssum[t + 1];
        if (Sb >= target && Sb1 < target) s_chosen = t;
        __syncthreads();
        int chosen = s_chosen;
        prefix |= ((unsigned)chosen) << shift;
        if (t == 0) s_target = target - ((chosen == 255) ? 0 : ssum[chosen + 1]);
        __syncthreads();
    }
    unsigned T = prefix;
    int need_eq = s_target;
    int count_gt = NSEL - need_eq;

    // collect strictly-greater + count ties per thread (blocked distribution)
    int mytie = 0;
#pragma unroll
    for (int e2 = 0; e2 < 8; e2++) {
        int e = t * 8 + e2;
        unsigned u = ukey[e];
        if (u > T) {
            int p = atomicAdd(&cnt_gt, 1);
            selKey[p] = u; selIdx[p] = e;
        } else if (u == T) mytie++;
    }
    tcnt[t] = mytie;
    __syncthreads();
    // exclusive scan tie counts -> emit lowest-index ties
    {
        int x = tcnt[t];
#pragma unroll
        for (int o = 1; o < 32; o <<= 1) {
            int y = __shfl_up_sync(0xffffffffu, x, o);
            if (lane >= o) x += y;
        }
        if (lane == 31) wsum[w] = x;
        __syncthreads();
        if (w == 0 && lane < 8) {
            int y = wsum[lane];
#pragma unroll
            for (int o = 1; o < 8; o <<= 1) {
                int z = __shfl_up_sync(0xffu, y, o);
                if (lane >= o) y += z;
            }
            wsum[lane] = y;
        }
        __syncthreads();
        int run = x - tcnt[t] + (w > 0 ? wsum[w - 1] : 0);
#pragma unroll
        for (int e2 = 0; e2 < 8; e2++) {
            int e = t * 8 + e2;
            if (ukey[e] == T) {
                if (run < need_eq) { selKey[count_gt + run] = T; selIdx[count_gt + run] = e; }
                run++;
            }
        }
    }
    __syncthreads();
    // rank sort 40: (key desc, idx asc)
    if (t < NSEL) {
        unsigned mk = selKey[t]; int mi = selIdx[t];
        int rank = 0;
        for (int f = 0; f < NSEL; f++) {
            unsigned fk = selKey[f]; int fi = selIdx[f];
            if (fk > mk || (fk == mk && fi < mi)) rank++;
        }
        g_topidx[bh * NSEL + rank] = mi;
    }
}

// ============================================================================
// K3: logits = (q_sel @ k^T)*SCALE with causal mask (j > idx -> -inf),
// written to attn buffer; also per-row partial max / sumexp per 256-key split.
// grid (BH, 8), block 256. Register-tiled 40x128 per subtile.
// ============================================================================
__global__ void k_logits(const float* __restrict__ q,
                         const float* __restrict__ k,
                         float* __restrict__ attn) {
    __shared__ float qs[NSEL * DQ];        // 40x64
    __shared__ float ks[128 * 65];         // padded
    __shared__ int   sidx[NSEL];

    int bh = blockIdx.x, js = blockIdx.y, t = threadIdx.x;
    if (t < NSEL) sidx[t] = g_topidx[bh * NSEL + t];
    __syncthreads();

    for (int e = t; e < NSEL * DQ; e += 256) {
        int s = e >> 6, d = e & 63;
        qs[e] = q[((size_t)bh * LQ + sidx[s]) * DQ + d];
    }

    float* attnBH = attn + (size_t)bh * NSEL * LQ;
    int tx = t & 63, ty = t >> 6;   // tx: key col base, ty: 0..3 row group

    for (int sub = 0; sub < 2; sub++) {
        int j0 = js * 256 + sub * 128;
        __syncthreads();
        for (int e = t; e < 128 * DQ; e += 256) {
            int r = e >> 6, d = e & 63;
            ks[r * 65 + d] = k[((size_t)bh * LQ + j0 + r) * DQ + d];
        }
        __syncthreads();

        float acc[10][2];
#pragma unroll
        for (int r = 0; r < 10; r++) { acc[r][0] = 0.0f; acc[r][1] = 0.0f; }

#pragma unroll 4
        for (int d = 0; d < DQ; d++) {
            float k0 = ks[tx * 65 + d];
            float k1 = ks[(tx + 64) * 65 + d];
#pragma unroll
            for (int r = 0; r < 10; r++) {
                float qv = qs[(ty + 4 * r) * DQ + d];
                acc[r][0] = fmaf(qv, k0, acc[r][0]);
                acc[r][1] = fmaf(qv, k1, acc[r][1]);
            }
        }
#pragma unroll
        for (int r = 0; r < 10; r++) {
            int s = ty + 4 * r;
            int lim = sidx[s];
            int jg0 = j0 + tx;
            int jg1 = j0 + tx + 64;
            attnBH[(size_t)s * LQ + jg0] = (jg0 > lim) ? NEG_INF : acc[r][0] * SCALE;
            attnBH[(size_t)s * LQ + jg1] = (jg1 > lim) ? NEG_INF : acc[r][1] * SCALE;
        }
    }
    __syncthreads();   // make our global logit writes visible block-wide

    // partial softmax stats over this block's 256-key span
    int w = t >> 5, lane = t & 31;
    for (int rr = 0; rr < 5; rr++) {
        int s = w + 8 * rr;
        size_t base = (size_t)s * LQ + js * 256;
        float m = NEG_INF;
#pragma unroll
        for (int u = 0; u < 8; u++) m = fmaxf(m, attnBH[base + lane + 32 * u]);
        m = fmaxf(m, __shfl_xor_sync(0xffffffffu, m, 16));
        m = fmaxf(m, __shfl_xor_sync(0xffffffffu, m, 8));
        m = fmaxf(m, __shfl_xor_sync(0xffffffffu, m, 4));
        m = fmaxf(m, __shfl_xor_sync(0xffffffffu, m, 2));
        m = fmaxf(m, __shfl_xor_sync(0xffffffffu, m, 1));
        float ssum = 0.0f;
        if (m > NEG_INF) {
#pragma unroll
            for (int u = 0; u < 8; u++) ssum += expf(attnBH[base + lane + 32 * u] - m);
        }
        ssum += __shfl_xor_sync(0xffffffffu, ssum, 16);
        ssum += __shfl_xor_sync(0xffffffffu, ssum, 8);
        ssum += __shfl_xor_sync(0xffffffffu, ssum, 4);
        ssum += __shfl_xor_sync(0xffffffffu, ssum, 2);
        ssum += __shfl_xor_sync(0xffffffffu, ssum, 1);
        if (lane == 0) {
            g_rowMaxPart[(bh * 8 + js) * NSEL + s] = m;
            g_rowSumPart[(bh * 8 + js) * NSEL + s] = ssum;
        }
    }
}

// ============================================================================
// K3b: combine partial stats -> final rowMax / 1/rowSum; zero outSel scratch
// ============================================================================
__global__ void k_combine() {
    int bh = blockIdx.x, t = threadIdx.x;
    if (t < NSEL) {
        float fm = NEG_INF;
#pragma unroll
        for (int p = 0; p < 8; p++)
            fm = fmaxf(fm, g_rowMaxPart[(bh * 8 + p) * NSEL + t]);
        float fs = 0.0f;
#pragma unroll
        for (int p = 0; p < 8; p++) {
            float pm = g_rowMaxPart[(bh * 8 + p) * NSEL + t];
            float ps = g_rowSumPart[(bh * 8 + p) * NSEL + t];
            fs += ps * expf(pm - fm);
        }
        g_rowMax[bh * NSEL + t] = fm;
        g_rowInv[bh * NSEL + t] = 1.0f / fs;
    }
    for (int e = t; e < NSEL * DQ; e += 64) g_outSel[bh * NSEL * DQ + e] = 0.0f;
}

// ============================================================================
// cumsum(v, axis=L): 3-pass chunk scan (chunk = 128 rows, 16 chunks)
// ============================================================================
__global__ void k_csumA(const float* __restrict__ v) {       // grid (BH,16), 256 thr
    int bh = blockIdx.x, c = blockIdx.y, t = threadIdx.x;
    int d = t & 63, g = t >> 6;
    const float* base = v + ((size_t)bh * LQ + c * 128) * DQ;
    float s = 0.0f;
#pragma unroll 8
    for (int r = g * 32; r < g * 32 + 32; r++) s += base[(size_t)r * DQ + d];
    __shared__ float red[256];
    red[t] = s;
    __syncthreads();
    if (g == 0)
        g_chunkSum[(bh * 16 + c) * DQ + d] = red[d] + red[64 + d] + red[128 + d] + red[192 + d];
}

__global__ void k_csumB() {                                  // grid BH, 64 thr
    int bh = blockIdx.x, d = threadIdx.x;
    float run = 0.0f;
#pragma unroll
    for (int c = 0; c < 16; c++) {
        float x = g_chunkSum[(bh * 16 + c) * DQ + d];
        g_chunkSum[(bh * 16 + c) * DQ + d] = run;   // exclusive
        run += x;
    }
}

__global__ void k_csumC(const float* __restrict__ v, float* __restrict__ out) { // grid (BH,16), 64 thr
    int bh = blockIdx.x, c = blockIdx.y, d = threadIdx.x;
    const float* base = v + ((size_t)bh * LQ + c * 128) * DQ;
    float* obase = out + ((size_t)bh * LQ + c * 128) * DQ;
    float run = g_chunkSum[(bh * 16 + c) * DQ + d];
#pragma unroll 8
    for (int r = 0; r < 128; r++) {
        run += base[(size_t)r * DQ + d];
        obase[(size_t)r * DQ + d] = run;
    }
}

// ============================================================================
// K4: probs = softmax(logits) written in place to attn; out_sel += P @ V
// grid (BH, 4 jsplits of 512 keys), block 256. 8 inner tiles of 64 keys.
// ============================================================================
__global__ void k_pv(const float* __restrict__ v, float* __restrict__ attn) {
    __shared__ float vs[64 * DQ];     // 16 KB
    __shared__ float ps[NSEL * 64];   // 10 KB
    __shared__ float sMax[NSEL], sInv[NSEL];

    int bh = blockIdx.x, js = blockIdx.y, t = threadIdx.x;
    if (t < NSEL) { sMax[t] = g_rowMax[bh * NSEL + t]; sInv[t] = g_rowInv[bh * NSEL + t]; }

    float* attnBH = attn + (size_t)bh * NSEL * LQ;
    const float* vBH = v + (size_t)bh * LQ * DQ;

    int tx = t & 31, ty = t >> 5;
    int g = ty >> 2;       // jj half
    int sy = ty & 3;       // row group

    float acc[10][2];
#pragma unroll
    for (int r = 0; r < 10; r++) { acc[r][0] = 0.0f; acc[r][1] = 0.0f; }
    __syncthreads();

    for (int tile = 0; tile < 8; tile++) {
        int j0 = js * 512 + tile * 64;
        __syncthreads();
        const float4* vsrc = reinterpret_cast<const float4*>(vBH + (size_t)j0 * DQ);
        float4* vdst = reinterpret_cast<float4*>(vs);
        for (int e = t; e < 64 * DQ / 4; e += 256) vdst[e] = vsrc[e];
        for (int e = t; e < NSEL * 64; e += 256) {
            int s = e >> 6, jj = e & 63;
            size_t a = (size_t)s * LQ + j0 + jj;
            float l = attnBH[a];
            float p = expf(l - sMax[s]) * sInv[s];
            attnBH[a] = p;
            ps[e] = p;
        }
        __syncthreads();
#pragma unroll 4
        for (int jl = g * 32; jl < g * 32 + 32; jl++) {
            float2 vv = *reinterpret_cast<const float2*>(&vs[jl * DQ + 2 * tx]);
#pragma unroll
            for (int r = 0; r < 10; r++) {
                float p = ps[(sy + 4 * r) * 64 + jl];
                acc[r][0] = fmaf(p, vv.x, acc[r][0]);
                acc[r][1] = fmaf(p, vv.y, acc[r][1]);
            }
        }
    }
#pragma unroll
    for (int r = 0; r < 10; r++) {
        int s = sy + 4 * r;
        atomicAdd(&g_outSel[(bh * NSEL + s) * DQ + 2 * tx], acc[r][0]);
        atomicAdd(&g_outSel[(bh * NSEL + s) * DQ + 2 * tx + 1], acc[r][1]);
    }
}

// ============================================================================
// K6: scatter out_sel rows into out at the selected positions
// ============================================================================
__global__ void k_scatter(float* __restrict__ out) {   // grid BH, 256 thr
    int bh = blockIdx.x, t = threadIdx.x;
    for (int e = t; e < NSEL * DQ; e += 256) {
        int s = e >> 6, d = e & 63;
        out[((size_t)bh * LQ + g_topidx[bh * NSEL + s]) * DQ + d] =
            g_outSel[bh * NSEL * DQ + e];
    }
}

// ============================================================================
extern "C" void kernel_launch(void* const* d_in, const int* in_sizes, int n_in,
                              void* d_out, int out_size) {
    const float* q = (const float*)d_in[0];
    const float* k = (const float*)d_in[1];
    const float* v = (const float*)d_in[2];
    const int* ridx = (const int*)d_in[3];

    float* out  = (float*)d_out;                        // [BH, L, D]
    float* attn = out + (size_t)BH * LQ * DQ;           // [BH, NSEL, L]

    // Launch order puts k_measure at position 4 so ncu (-s) samples it.
    // cumsum chain first (depends only on v).
    {
        dim3 grid(BH, 16);
        k_csumA<<<grid, 256>>>(v);
        k_csumB<<<BH, 64>>>();
        k_csumC<<<grid, 64>>>(v, out);
    }
    // 1. measure (warp-per-query, 4-way interleaved gather)
    k_measure<<<(BH * LQ) / 8, 256>>>(q, k, ridx);
    // 2. top-k selection (radix select)
    k_topk<<<BH, 256>>>();
    // 3. logits + partial softmax stats
    {
        dim3 grid(BH, 8);
        k_logits<<<grid, 256>>>(q, k, attn);
    }
    // 3b. combine stats, zero out_sel
    k_combine<<<BH, 64>>>();
    // 4. softmax probs (in place) + P@V partial accumulation
    {
        dim3 grid(BH, 4);
        k_pv<<<grid, 256>>>(v, attn);
    }
    // 6. scatter selected rows into out
    k_scatter<<<BH, 256>>>(out);
}

// round 5
// speedup vs baseline: 2.9362x; 1.3979x over previous
#include <cuda_runtime.h>
#include <cuda_bf16.h>
#include <math.h>
#include <math_constants.h>

// Problem constants
#define BQ  8
#define HQ  8
#define BH  64          // B*H
#define LQ  2048
#define DQ  64
#define NSEL 40         // num selected queries == num sampled keys
#define SCALE 0.125f    // 64^-0.5
#define NEG_INF (-CUDART_INF_F)

// ---------------- scratch (device globals; no allocation allowed) ----------
__device__ float g_measure[BH * LQ];
__device__ int   g_topidx[BH * NSEL];
__device__ float g_rowMaxPart[BH * 8 * NSEL];
__device__ float g_rowSumPart[BH * 8 * NSEL];
__device__ float g_rowMax[BH * NSEL];
__device__ float g_rowInv[BH * NSEL];
__device__ float g_outSel[BH * NSEL * DQ];
__device__ float g_chunkSum[BH * 16 * DQ];

// ============================================================================
// K1: measure[bh][i] = max_j (q_i . k_{ridx[i,j]}) - (sum_j ...) / L
// Warp per query; 8 lanes per key (4 keys per load/shuffle step).
// Lane 8g+p loads float4 halves of key (4h+g)'s row -> each 8-lane group reads
// one contiguous 128B line per LDG (wavefronts unchanged), and the dot needs
// only a 3-step butterfly. SHFL count per warp: ~34 vs ~210 before.
// ============================================================================
__global__ __launch_bounds__(256) void k_measure(const float* __restrict__ q,
                                                 const float* __restrict__ k,
                                                 const int* __restrict__ ridx) {
    const unsigned F = 0xffffffffu;
    int warp = (blockIdx.x * blockDim.x + threadIdx.x) >> 5;
    int lane = threadIdx.x & 31;
    int bh = warp >> 11;
    int i  = warp & 2047;
    int grp = lane >> 3;          // which key of the quad
    int p   = lane & 7;           // float4 slot within 32-dim half

    const float4* qrow = reinterpret_cast<const float4*>(q + ((size_t)bh * LQ + i) * DQ);
    float4 qv0 = qrow[p];         // dims [4p, 4p+4)
    float4 qv1 = qrow[8 + p];     // dims [32+4p, 32+4p+4)
    const float4* kb4 = reinterpret_cast<const float4*>(k + (size_t)bh * LQ * DQ);
    const int* rbase = ridx + i * NSEL + grp;

    float m = NEG_INF, s = 0.0f;
#pragma unroll
    for (int h = 0; h < NSEL / 4; h += 2) {
        int ra = rbase[4 * h];            // key 4h+grp
        int rb = rbase[4 * h + 4];        // key 4(h+1)+grp
        const float4* kra = kb4 + (size_t)ra * (DQ / 4);
        const float4* krb = kb4 + (size_t)rb * (DQ / 4);
        float4 a0 = kra[p];
        float4 a1 = kra[8 + p];
        float4 b0 = krb[p];
        float4 b1 = krb[8 + p];
        float da = qv0.x * a0.x + qv0.y * a0.y + qv0.z * a0.z + qv0.w * a0.w;
        da += qv1.x * a1.x + qv1.y * a1.y + qv1.z * a1.z + qv1.w * a1.w;
        float db = qv0.x * b0.x + qv0.y * b0.y + qv0.z * b0.z + qv0.w * b0.w;
        db += qv1.x * b1.x + qv1.y * b1.y + qv1.z * b1.z + qv1.w * b1.w;
        // 3-step butterfly within the 8-lane group (bits 0..2)
        da += __shfl_xor_sync(F, da, 1);
        db += __shfl_xor_sync(F, db, 1);
        da += __shfl_xor_sync(F, da, 2);
        db += __shfl_xor_sync(F, db, 2);
        da += __shfl_xor_sync(F, da, 4);
        db += __shfl_xor_sync(F, db, 4);
        m = fmaxf(m, fmaxf(da, db));
        s += da + db;
    }
    // combine across the 4 groups (bits 3,4). Within a group all lanes hold
    // identical (m,s), so reducing only across bits 3,4 avoids overcounting.
    m = fmaxf(m, __shfl_xor_sync(F, m, 8));
    s += __shfl_xor_sync(F, s, 8);
    m = fmaxf(m, __shfl_xor_sync(F, m, 16));
    s += __shfl_xor_sync(F, s, 16);
    if (lane == 0) g_measure[bh * LQ + i] = m - s * (1.0f / (float)LQ);
}

// ============================================================================
// K2: per (b,h) top-40 of 2048 via 4-pass byte radix select + rank sort.
// Matches jax.lax.top_k: descending value, ties -> lower index first.
// One block (256 thr) per bh.
// ============================================================================
__global__ void k_topk() {
    __shared__ unsigned ukey[LQ];
    __shared__ int hist[256];
    __shared__ int ssum[256];
    __shared__ int wsum[8];
    __shared__ int s_chosen;
    __shared__ int s_target;
    __shared__ int cnt_gt;
    __shared__ unsigned selKey[64];
    __shared__ int selIdx[64];
    __shared__ int tcnt[256];

    int bh = blockIdx.x, t = threadIdx.x, lane = t & 31, w = t >> 5;

    for (int e = t; e < LQ; e += 256) {
        unsigned b = __float_as_uint(g_measure[bh * LQ + e]);
        ukey[e] = (b & 0x80000000u) ? ~b : (b | 0x80000000u);
    }
    if (t == 0) { s_target = NSEL; cnt_gt = 0; }
    __syncthreads();

    unsigned prefix = 0;
    for (int pass = 3; pass >= 0; pass--) {
        int shift = pass * 8;
        hist[t] = 0;
        __syncthreads();
        unsigned himask = (pass == 3) ? 0u : (0xFFFFFFFFu << (shift + 8));
        for (int e = t; e < LQ; e += 256) {
            unsigned u = ukey[e];
            if ((u & himask) == (prefix & himask))
                atomicAdd(&hist[(u >> shift) & 255], 1);
        }
        __syncthreads();
        // suffix sums S[b] = count of candidate keys with byte >= b
        int r = 255 - t;
        int x = hist[r];
#pragma unroll
        for (int o = 1; o < 32; o <<= 1) {
            int y = __shfl_up_sync(0xffffffffu, x, o);
            if (lane >= o) x += y;
        }
        if (lane == 31) wsum[w] = x;
        __syncthreads();
        if (w == 0 && lane < 8) {
            int y = wsum[lane];
#pragma unroll
            for (int o = 1; o < 8; o <<= 1) {
                int z = __shfl_up_sync(0xffu, y, o);
                if (lane >= o) y += z;
            }
            wsum[lane] = y;
        }
        __syncthreads();
        int S = x + (w > 0 ? wsum[w - 1] : 0);
        ssum[r] = S;
        __syncthreads();
        int target = s_target;
        int Sb = ssum[t];
        int Sb1 = (t == 255) ? 0 : ssum[t + 1];
        if (Sb >= target && Sb1 < target) s_chosen = t;
        __syncthreads();
        int chosen = s_chosen;
        prefix |= ((unsigned)chosen) << shift;
        if (t == 0) s_target = target - ((chosen == 255) ? 0 : ssum[chosen + 1]);
        __syncthreads();
    }
    unsigned T = prefix;
    int need_eq = s_target;
    int count_gt = NSEL - need_eq;

    // collect strictly-greater + count ties per thread (blocked distribution)
    int mytie = 0;
#pragma unroll
    for (int e2 = 0; e2 < 8; e2++) {
        int e = t * 8 + e2;
        unsigned u = ukey[e];
        if (u > T) {
            int p = atomicAdd(&cnt_gt, 1);
            selKey[p] = u; selIdx[p] = e;
        } else if (u == T) mytie++;
    }
    tcnt[t] = mytie;
    __syncthreads();
    // exclusive scan tie counts -> emit lowest-index ties
    {
        int x = tcnt[t];
#pragma unroll
        for (int o = 1; o < 32; o <<= 1) {
            int y = __shfl_up_sync(0xffffffffu, x, o);
            if (lane >= o) x += y;
        }
        if (lane == 31) wsum[w] = x;
        __syncthreads();
        if (w == 0 && lane < 8) {
            int y = wsum[lane];
#pragma unroll
            for (int o = 1; o < 8; o <<= 1) {
                int z = __shfl_up_sync(0xffu, y, o);
                if (lane >= o) y += z;
            }
            wsum[lane] = y;
        }
        __syncthreads();
        int run = x - tcnt[t] + (w > 0 ? wsum[w - 1] : 0);
#pragma unroll
        for (int e2 = 0; e2 < 8; e2++) {
            int e = t * 8 + e2;
            if (ukey[e] == T) {
                if (run < need_eq) { selKey[count_gt + run] = T; selIdx[count_gt + run] = e; }
                run++;
            }
        }
    }
    __syncthreads();
    // rank sort 40: (key desc, idx asc)
    if (t < NSEL) {
        unsigned mk = selKey[t]; int mi = selIdx[t];
        int rank = 0;
        for (int f = 0; f < NSEL; f++) {
            unsigned fk = selKey[f]; int fi = selIdx[f];
            if (fk > mk || (fk == mk && fi < mi)) rank++;
        }
        g_topidx[bh * NSEL + rank] = mi;
    }
}

// ============================================================================
// K3: logits = (q_sel @ k^T)*SCALE with causal mask (j > idx -> -inf),
// written to attn buffer; also per-row partial max / sumexp per 256-key split.
// grid (BH, 8), block 256. Register-tiled 40x128 per subtile.
// ============================================================================
__global__ void k_logits(const float* __restrict__ q,
                         const float* __restrict__ k,
                         float* __restrict__ attn) {
    __shared__ float qs[NSEL * DQ];        // 40x64
    __shared__ float ks[128 * 65];         // padded
    __shared__ int   sidx[NSEL];

    int bh = blockIdx.x, js = blockIdx.y, t = threadIdx.x;
    if (t < NSEL) sidx[t] = g_topidx[bh * NSEL + t];
    __syncthreads();

    for (int e = t; e < NSEL * DQ; e += 256) {
        int s = e >> 6, d = e & 63;
        qs[e] = q[((size_t)bh * LQ + sidx[s]) * DQ + d];
    }

    float* attnBH = attn + (size_t)bh * NSEL * LQ;
    int tx = t & 63, ty = t >> 6;   // tx: key col base, ty: 0..3 row group

    for (int sub = 0; sub < 2; sub++) {
        int j0 = js * 256 + sub * 128;
        __syncthreads();
        for (int e = t; e < 128 * DQ; e += 256) {
            int r = e >> 6, d = e & 63;
            ks[r * 65 + d] = k[((size_t)bh * LQ + j0 + r) * DQ + d];
        }
        __syncthreads();

        float acc[10][2];
#pragma unroll
        for (int r = 0; r < 10; r++) { acc[r][0] = 0.0f; acc[r][1] = 0.0f; }

#pragma unroll 4
        for (int d = 0; d < DQ; d++) {
            float k0 = ks[tx * 65 + d];
            float k1 = ks[(tx + 64) * 65 + d];
#pragma unroll
            for (int r = 0; r < 10; r++) {
                float qv = qs[(ty + 4 * r) * DQ + d];
                acc[r][0] = fmaf(qv, k0, acc[r][0]);
                acc[r][1] = fmaf(qv, k1, acc[r][1]);
            }
        }
#pragma unroll
        for (int r = 0; r < 10; r++) {
            int s = ty + 4 * r;
            int lim = sidx[s];
            int jg0 = j0 + tx;
            int jg1 = j0 + tx + 64;
            attnBH[(size_t)s * LQ + jg0] = (jg0 > lim) ? NEG_INF : acc[r][0] * SCALE;
            attnBH[(size_t)s * LQ + jg1] = (jg1 > lim) ? NEG_INF : acc[r][1] * SCALE;
        }
    }
    __syncthreads();   // make our global logit writes visible block-wide

    // partial softmax stats over this block's 256-key span
    int w = t >> 5, lane = t & 31;
    for (int rr = 0; rr < 5; rr++) {
        int s = w + 8 * rr;
        size_t base = (size_t)s * LQ + js * 256;
        float m = NEG_INF;
#pragma unroll
        for (int u = 0; u < 8; u++) m = fmaxf(m, attnBH[base + lane + 32 * u]);
        m = fmaxf(m, __shfl_xor_sync(0xffffffffu, m, 16));
        m = fmaxf(m, __shfl_xor_sync(0xffffffffu, m, 8));
        m = fmaxf(m, __shfl_xor_sync(0xffffffffu, m, 4));
        m = fmaxf(m, __shfl_xor_sync(0xffffffffu, m, 2));
        m = fmaxf(m, __shfl_xor_sync(0xffffffffu, m, 1));
        float ssum = 0.0f;
        if (m > NEG_INF) {
#pragma unroll
            for (int u = 0; u < 8; u++) ssum += expf(attnBH[base + lane + 32 * u] - m);
        }
        ssum += __shfl_xor_sync(0xffffffffu, ssum, 16);
        ssum += __shfl_xor_sync(0xffffffffu, ssum, 8);
        ssum += __shfl_xor_sync(0xffffffffu, ssum, 4);
        ssum += __shfl_xor_sync(0xffffffffu, ssum, 2);
        ssum += __shfl_xor_sync(0xffffffffu, ssum, 1);
        if (lane == 0) {
            g_rowMaxPart[(bh * 8 + js) * NSEL + s] = m;
            g_rowSumPart[(bh * 8 + js) * NSEL + s] = ssum;
        }
    }
}

// ============================================================================
// K3b: combine partial stats -> final rowMax / 1/rowSum; zero outSel scratch
// ============================================================================
__global__ void k_combine() {
    int bh = blockIdx.x, t = threadIdx.x;
    if (t < NSEL) {
        float fm = NEG_INF;
#pragma unroll
        for (int p = 0; p < 8; p++)
            fm = fmaxf(fm, g_rowMaxPart[(bh * 8 + p) * NSEL + t]);
        float fs = 0.0f;
#pragma unroll
        for (int p = 0; p < 8; p++) {
            float pm = g_rowMaxPart[(bh * 8 + p) * NSEL + t];
            float ps = g_rowSumPart[(bh * 8 + p) * NSEL + t];
            fs += ps * expf(pm - fm);
        }
        g_rowMax[bh * NSEL + t] = fm;
        g_rowInv[bh * NSEL + t] = 1.0f / fs;
    }
    for (int e = t; e < NSEL * DQ; e += 64) g_outSel[bh * NSEL * DQ + e] = 0.0f;
}

// ============================================================================
// cumsum(v, axis=L): 3-pass chunk scan (chunk = 128 rows, 16 chunks)
// ============================================================================
__global__ void k_csumA(const float* __restrict__ v) {       // grid (BH,16), 256 thr
    int bh = blockIdx.x, c = blockIdx.y, t = threadIdx.x;
    int d = t & 63, g = t >> 6;
    const float* base = v + ((size_t)bh * LQ + c * 128) * DQ;
    float s = 0.0f;
#pragma unroll 8
    for (int r = g * 32; r < g * 32 + 32; r++) s += base[(size_t)r * DQ + d];
    __shared__ float red[256];
    red[t] = s;
    __syncthreads();
    if (g == 0)
        g_chunkSum[(bh * 16 + c) * DQ + d] = red[d] + red[64 + d] + red[128 + d] + red[192 + d];
}

__global__ void k_csumB() {                                  // grid BH, 64 thr
    int bh = blockIdx.x, d = threadIdx.x;
    float run = 0.0f;
#pragma unroll
    for (int c = 0; c < 16; c++) {
        float x = g_chunkSum[(bh * 16 + c) * DQ + d];
        g_chunkSum[(bh * 16 + c) * DQ + d] = run;   // exclusive
        run += x;
    }
}

__global__ void k_csumC(const float* __restrict__ v, float* __restrict__ out) { // grid (BH,16), 64 thr
    int bh = blockIdx.x, c = blockIdx.y, d = threadIdx.x;
    const float* base = v + ((size_t)bh * LQ + c * 128) * DQ;
    float* obase = out + ((size_t)bh * LQ + c * 128) * DQ;
    float run = g_chunkSum[(bh * 16 + c) * DQ + d];
#pragma unroll 8
    for (int r = 0; r < 128; r++) {
        run += base[(size_t)r * DQ + d];
        obase[(size_t)r * DQ + d] = run;
    }
}

// ============================================================================
// K4: probs = softmax(logits) written in place to attn; out_sel += P @ V
// grid (BH, 4 jsplits of 512 keys), block 256. 8 inner tiles of 64 keys.
// ============================================================================
__global__ void k_pv(const float* __restrict__ v, float* __restrict__ attn) {
    __shared__ float vs[64 * DQ];     // 16 KB
    __shared__ float ps[NSEL * 64];   // 10 KB
    __shared__ float sMax[NSEL], sInv[NSEL];

    int bh = blockIdx.x, js = blockIdx.y, t = threadIdx.x;
    if (t < NSEL) { sMax[t] = g_rowMax[bh * NSEL + t]; sInv[t] = g_rowInv[bh * NSEL + t]; }

    float* attnBH = attn + (size_t)bh * NSEL * LQ;
    const float* vBH = v + (size_t)bh * LQ * DQ;

    int tx = t & 31, ty = t >> 5;
    int g = ty >> 2;       // jj half
    int sy = ty & 3;       // row group

    float acc[10][2];
#pragma unroll
    for (int r = 0; r < 10; r++) { acc[r][0] = 0.0f; acc[r][1] = 0.0f; }
    __syncthreads();

    for (int tile = 0; tile < 8; tile++) {
        int j0 = js * 512 + tile * 64;
        __syncthreads();
        const float4* vsrc = reinterpret_cast<const float4*>(vBH + (size_t)j0 * DQ);
        float4* vdst = reinterpret_cast<float4*>(vs);
        for (int e = t; e < 64 * DQ / 4; e += 256) vdst[e] = vsrc[e];
        for (int e = t; e < NSEL * 64; e += 256) {
            int s = e >> 6, jj = e & 63;
            size_t a = (size_t)s * LQ + j0 + jj;
            float l = attnBH[a];
            float p = expf(l - sMax[s]) * sInv[s];
            attnBH[a] = p;
            ps[e] = p;
        }
        __syncthreads();
#pragma unroll 4
        for (int jl = g * 32; jl < g * 32 + 32; jl++) {
            float2 vv = *reinterpret_cast<const float2*>(&vs[jl * DQ + 2 * tx]);
#pragma unroll
            for (int r = 0; r < 10; r++) {
                float p = ps[(sy + 4 * r) * 64 + jl];
                acc[r][0] = fmaf(p, vv.x, acc[r][0]);
                acc[r][1] = fmaf(p, vv.y, acc[r][1]);
            }
        }
    }
#pragma unroll
    for (int r = 0; r < 10; r++) {
        int s = sy + 4 * r;
        atomicAdd(&g_outSel[(bh * NSEL + s) * DQ + 2 * tx], acc[r][0]);
        atomicAdd(&g_outSel[(bh * NSEL + s) * DQ + 2 * tx + 1], acc[r][1]);
    }
}

// ============================================================================
// K6: scatter out_sel rows into out at the selected positions
// ============================================================================
__global__ void k_scatter(float* __restrict__ out) {   // grid BH, 256 thr
    int bh = blockIdx.x, t = threadIdx.x;
    for (int e = t; e < NSEL * DQ; e += 256) {
        int s = e >> 6, d = e & 63;
        out[((size_t)bh * LQ + g_topidx[bh * NSEL + s]) * DQ + d] =
            g_outSel[bh * NSEL * DQ + e];
    }
}

// ============================================================================
extern "C" void kernel_launch(void* const* d_in, const int* in_sizes, int n_in,
                              void* d_out, int out_size) {
    const float* q = (const float*)d_in[0];
    const float* k = (const float*)d_in[1];
    const float* v = (const float*)d_in[2];
    const int* ridx = (const int*)d_in[3];

    float* out  = (float*)d_out;                        // [BH, L, D]
    float* attn = out + (size_t)BH * LQ * DQ;           // [BH, NSEL, L]

    // Launch order puts k_measure at position 4 so ncu (-s) samples it.
    // cumsum chain first (depends only on v).
    {
        dim3 grid(BH, 16);
        k_csumA<<<grid, 256>>>(v);
        k_csumB<<<BH, 64>>>();
        k_csumC<<<grid, 64>>>(v, out);
    }
    // 1. measure (warp-per-query, 8-lane-per-key gather)
    k_measure<<<(BH * LQ) / 8, 256>>>(q, k, ridx);
    // 2. top-k selection (radix select)
    k_topk<<<BH, 256>>>();
    // 3. logits + partial softmax stats
    {
        dim3 grid(BH, 8);
        k_logits<<<grid, 256>>>(q, k, attn);
    }
    // 3b. combine stats, zero out_sel
    k_combine<<<BH, 64>>>();
    // 4. softmax probs (in place) + P@V partial accumulation
    {
        dim3 grid(BH, 4);
        k_pv<<<grid, 256>>>(v, attn);
    }
    // 6. scatter selected rows into out
    k_scatter<<<BH, 256>>>(out);
}